// round 1
// baseline (speedup 1.0000x reference)
#include <cuda_runtime.h>
#include <cstdint>

// Problem shapes (fixed for this problem instance)
#define T_TOK 2048   // S*B tokens
#define HID   1024   // H
#define FF    4096   // F
#define NE    4      // experts
// Inputs (metadata order): 0 hidden_states [S,B,H] f32, 1 mlp_residual f32,
// 2 probs [T,E] f32 (exactly 0 where unrouted), 3 routing_map (unused),
// 4 w1 [E,H,F] f32, 5 w2 [E,F,H] f32. Output: [S,B,H] f32.

// -------- scratch (device globals: allocation-guard-safe) --------
__device__ int   g_cnt[NE];
__device__ int   g_idx[NE * T_TOK];
__device__ float g_gate[NE * T_TOK];
__device__ float g_act[(size_t)NE * T_TOK * FF];   // 128 MiB fp32 scratch

// -------- helpers --------
__device__ __forceinline__ uint32_t f2tf(float x) {
    uint32_t u;
    asm("cvt.rna.tf32.f32 %0, %1;" : "=r"(u) : "f"(x));
    return u;
}

__device__ __forceinline__ void mma_tf32(float* d, const uint32_t* a, const uint32_t* b) {
    asm volatile(
        "mma.sync.aligned.m16n8k8.row.col.f32.tf32.tf32.f32 "
        "{%0,%1,%2,%3}, {%4,%5,%6,%7}, {%8,%9}, {%0,%1,%2,%3};\n"
        : "+f"(d[0]), "+f"(d[1]), "+f"(d[2]), "+f"(d[3])
        : "r"(a[0]), "r"(a[1]), "r"(a[2]), "r"(a[3]), "r"(b[0]), "r"(b[1]));
}

__device__ __forceinline__ void cp_async16(float* dst, const float* src) {
    uint32_t d = (uint32_t)__cvta_generic_to_shared(dst);
    asm volatile("cp.async.cg.shared.global [%0], [%1], 16;\n" :: "r"(d), "l"(src));
}

__device__ __forceinline__ float gelu_exact(float v) {
    return 0.5f * v * (1.0f + erff(v * 0.70710678118654752f));
}

// -------- kernel 1: out = residual, zero counters --------
__global__ void init_kernel(const float* __restrict__ res, float* __restrict__ out) {
    if (blockIdx.x == 0 && threadIdx.x < NE) g_cnt[threadIdx.x] = 0;
    int i = blockIdx.x * blockDim.x + threadIdx.x;          // float4 index
    if (i < (T_TOK * HID) / 4)
        reinterpret_cast<float4*>(out)[i] = reinterpret_cast<const float4*>(res)[i];
}

// -------- kernel 2: routing lists from probs>0 --------
__global__ void route_kernel(const float* __restrict__ probs) {
    int t = blockIdx.x * blockDim.x + threadIdx.x;
    if (t >= T_TOK) return;
    #pragma unroll
    for (int e = 0; e < NE; e++) {
        float p = probs[t * NE + e];
        if (p > 0.f) {
            int pos = atomicAdd(&g_cnt[e], 1);
            g_idx[e * T_TOK + pos]  = t;
            g_gate[e * T_TOK + pos] = p;
        }
    }
}

// -------- GEMM (tf32 mma.sync, 128x128x32 tiles, cp.async double buffer) --------
// MODE 0: fc1  A = x[gather], B = w1[e] (H x F), epilogue gelu -> g_act
// MODE 1: fc2  A = g_act,     B = w2[e] (F x H), epilogue gate*atomicAdd -> out
#define ASZ 4608   /* 128 * 36 floats per buffer */
#define BSZ 4352   /* 32 * 136 floats per buffer */
#define SMEM_BYTES ((2 * ASZ + 2 * BSZ) * 4)   /* 71680 */

template <int MODE>
__global__ __launch_bounds__(256, 2)
void gemm_kernel(const float* __restrict__ X, const float* __restrict__ W,
                 float* __restrict__ OUT) {
    const int e  = blockIdx.z;
    const int m0 = blockIdx.y * 128;
    const int n0 = blockIdx.x * 128;
    const int cnt = g_cnt[e];
    if (m0 >= cnt) return;

    constexpr int K   = (MODE == 0) ? HID : FF;
    constexpr int LDB = (MODE == 0) ? FF  : HID;
    const float* Wp = W + (size_t)e * HID * FF;   // per-expert stride = H*F for both

    extern __shared__ float smem[];
    float* As = smem;             // [2][128][36]
    float* Bs = smem + 2 * ASZ;   // [2][32][136]
    __shared__ int   s_tok[128];
    __shared__ float s_gate[128];

    const int tid = threadIdx.x;
    if (tid < 128) {
        int m = m0 + tid;
        bool v = (m < cnt);
        s_tok[tid]  = v ? g_idx[e * T_TOK + m] : 0;
        s_gate[tid] = (MODE == 1 && v) ? g_gate[e * T_TOK + m] : 0.f;
    }
    __syncthreads();

    const int ar = tid >> 3, ac = tid & 7;    // A loads: 32 rows/pass, 8 float4 per row
    const int br = tid >> 5, bc = tid & 31;   // B loads: 8 rows/pass, 32 float4 per row

    auto load_tile = [&](int kt, int buf) {
        const int k0 = kt * 32;
        #pragma unroll
        for (int p = 0; p < 4; p++) {
            int row = ar + p * 32;
            const float* src;
            if (MODE == 0)
                src = X + (size_t)s_tok[row] * HID + k0 + ac * 4;
            else
                src = g_act + ((size_t)(e * T_TOK + m0 + row)) * FF + k0 + ac * 4;
            cp_async16(As + buf * ASZ + row * 36 + ac * 4, src);
        }
        #pragma unroll
        for (int p = 0; p < 4; p++) {
            int row = br + p * 8;
            const float* src = Wp + (size_t)(k0 + row) * LDB + n0 + bc * 4;
            cp_async16(Bs + buf * BSZ + row * 136 + bc * 4, src);
        }
        asm volatile("cp.async.commit_group;\n" ::: "memory");
    };

    const int lane = tid & 31;
    const int w    = tid >> 5;
    const int wm   = (w & 1) * 64;   // 2 warps along M (64 each)
    const int wn   = (w >> 1) * 32;  // 4 warps along N (32 each)
    const int g    = lane >> 2;      // groupID
    const int tg   = lane & 3;       // threadID_in_group

    float acc[4][4][4];
    #pragma unroll
    for (int i = 0; i < 4; i++)
        #pragma unroll
        for (int j = 0; j < 4; j++)
            #pragma unroll
            for (int q = 0; q < 4; q++) acc[i][j][q] = 0.f;

    constexpr int KT = K / 32;
    load_tile(0, 0);

    for (int kt = 0; kt < KT; ++kt) {
        asm volatile("cp.async.wait_group 0;\n" ::: "memory");
        __syncthreads();
        if (kt + 1 < KT) load_tile(kt + 1, (kt + 1) & 1);

        const float* Ab = As + (kt & 1) * ASZ;
        const float* Bb = Bs + (kt & 1) * BSZ;

        #pragma unroll
        for (int kk = 0; kk < 4; kk++) {
            const int k = kk * 8;
            uint32_t a[4][4], b[4][2];
            #pragma unroll
            for (int mf = 0; mf < 4; mf++) {
                int r = wm + mf * 16 + g;
                a[mf][0] = f2tf(Ab[(r)     * 36 + k + tg]);
                a[mf][1] = f2tf(Ab[(r + 8) * 36 + k + tg]);
                a[mf][2] = f2tf(Ab[(r)     * 36 + k + tg + 4]);
                a[mf][3] = f2tf(Ab[(r + 8) * 36 + k + tg + 4]);
            }
            #pragma unroll
            for (int nf = 0; nf < 4; nf++) {
                int c = wn + nf * 8 + g;
                b[nf][0] = f2tf(Bb[(k + tg)     * 136 + c]);
                b[nf][1] = f2tf(Bb[(k + tg + 4) * 136 + c]);
            }
            #pragma unroll
            for (int mf = 0; mf < 4; mf++)
                #pragma unroll
                for (int nf = 0; nf < 4; nf++)
                    mma_tf32(acc[mf][nf], a[mf], b[nf]);
        }
        __syncthreads();
    }

    // epilogue
    #pragma unroll
    for (int mf = 0; mf < 4; mf++) {
        #pragma unroll
        for (int i2 = 0; i2 < 2; i2++) {
            const int r = wm + mf * 16 + g + i2 * 8;
            const int grow = m0 + r;
            if (grow < cnt) {
                #pragma unroll
                for (int nf = 0; nf < 4; nf++) {
                    float v0 = acc[mf][nf][i2 * 2 + 0];
                    float v1 = acc[mf][nf][i2 * 2 + 1];
                    const int c = n0 + wn + nf * 8 + tg * 2;
                    if (MODE == 0) {
                        float2 o = make_float2(gelu_exact(v0), gelu_exact(v1));
                        *reinterpret_cast<float2*>(
                            g_act + ((size_t)(e * T_TOK + grow)) * FF + c) = o;
                    } else {
                        const float gt = s_gate[r];
                        float* o = OUT + (size_t)s_tok[r] * HID + c;
                        atomicAdd(o,     gt * v0);
                        atomicAdd(o + 1, gt * v1);
                    }
                }
            }
        }
    }
}

// -------- launch --------
extern "C" void kernel_launch(void* const* d_in, const int* in_sizes, int n_in,
                              void* d_out, int out_size) {
    const float* hs    = (const float*)d_in[0];
    const float* res   = (const float*)d_in[1];
    const float* probs = (const float*)d_in[2];
    const float* w1    = (const float*)d_in[4];
    const float* w2    = (const float*)d_in[5];
    float* out = (float*)d_out;

    cudaFuncSetAttribute(gemm_kernel<0>, cudaFuncAttributeMaxDynamicSharedMemorySize, SMEM_BYTES);
    cudaFuncSetAttribute(gemm_kernel<1>, cudaFuncAttributeMaxDynamicSharedMemorySize, SMEM_BYTES);

    init_kernel<<<(T_TOK * HID / 4 + 255) / 256, 256>>>(res, out);
    route_kernel<<<(T_TOK + 255) / 256, 256>>>(probs);
    // fc1: N = F (32 tiles), M tiles = T/128 = 16, z = experts
    gemm_kernel<0><<<dim3(FF / 128, T_TOK / 128, NE), 256, SMEM_BYTES>>>(hs, w1, nullptr);
    // fc2: N = H (8 tiles)
    gemm_kernel<1><<<dim3(HID / 128, T_TOK / 128, NE), 256, SMEM_BYTES>>>(hs, w2, out);
}